// round 1
// baseline (speedup 1.0000x reference)
#include <cuda_runtime.h>

#define N_IN   4096
#define N_OUT  4096
#define N_BLKS 4096
#define BATCH  1024
#define BS     32
#define NB_I   (N_IN / BS)    // 128
#define NB_O   (N_OUT / BS)   // 128

#define B_TILE   256
#define XS_PITCH 33           // 2-way-conflict-free-ish pitch for row-major x tile

// Dense (ci, co) -> block index table. All (ci,co) pairs in the mask are
// distinct (sampled without replacement), so the scatter is race-free and
// deterministic.
__device__ int g_tbl[NB_I * NB_O];

__global__ void fill_tbl_kernel() {
    int i = blockIdx.x * blockDim.x + threadIdx.x;
    if (i < NB_I * NB_O) g_tbl[i] = -1;
}

__global__ void scatter_tbl_kernel(const int* __restrict__ ci,
                                   const int* __restrict__ co) {
    int n = blockIdx.x * blockDim.x + threadIdx.x;
    if (n < N_BLKS) g_tbl[ci[n] * NB_O + co[n]] = n;
}

__device__ __forceinline__ unsigned long long pack2(float lo, float hi) {
    unsigned long long r;
    asm("mov.b64 %0, {%1, %2};" : "=l"(r) : "f"(lo), "f"(hi));
    return r;
}

__device__ __forceinline__ void unpack2(unsigned long long v, float& lo, float& hi) {
    asm("mov.b64 {%0, %1}, %2;" : "=f"(lo), "=f"(hi) : "l"(v));
}

// Packed dual-fp32 FMA (Blackwell f32x2 pipe): d = a * b + d (elementwise on pairs)
__device__ __forceinline__ void fma2(unsigned long long& d, unsigned long long a,
                                     unsigned long long b) {
    asm("fma.rn.f32x2 %0, %1, %2, %0;" : "+l"(d) : "l"(a), "l"(b));
}

// One CTA computes out[bt*256 .. bt*256+255, cob*32 .. cob*32+31].
// Loops over the input block-rows cib that have a block mapping to column cob.
__global__ void __launch_bounds__(128, 3)
bs_main_kernel(const float* __restrict__ x, const float* __restrict__ kern,
               const float* __restrict__ bias, float* __restrict__ out) {
    __shared__ float xs[B_TILE * XS_PITCH];  // x tile, row-major, padded (33.8 KB)
    __shared__ float ks[BS * BS];            // 32x32 kernel block (4 KB)
    __shared__ int   stbl[NB_I];             // this column's block indices

    const int cob = blockIdx.x;   // output block column 0..127
    const int bt  = blockIdx.y;   // batch tile 0..3
    const int tid = threadIdx.x;

    const int rg = tid >> 2;      // 0..31: row group (rows rg + 32*i)
    const int cg = tid & 3;       // 0..3 : col group
    const int c0 = cg * 8;

    // stage this column of the block table (128 ints, one per thread)
    stbl[tid] = g_tbl[tid * NB_O + cob];

    // bias fragment
    float bb[8];
#pragma unroll
    for (int j = 0; j < 8; j++) bb[j] = bias[cob * BS + c0 + j];

    unsigned long long acc[8][4];
#pragma unroll
    for (int i = 0; i < 8; i++)
#pragma unroll
        for (int j = 0; j < 4; j++) acc[i][j] = 0ull;

    const float* xbase = x + (size_t)(bt * B_TILE) * N_IN;

    for (int cib = 0; cib < NB_I; cib++) {
        __syncthreads();               // covers stbl on iter 0, prev compute after
        int n = stbl[cib];
        if (n < 0) continue;

        // ---- stage x tile: rows [bt*256, +256), cols [cib*32, +32) ----
        const float* xb = xbase + cib * BS;
#pragma unroll
        for (int i = 0; i < 16; i++) {
            int id  = tid + i * 128;   // 0..2047 float4 slots
            int row = id >> 3;
            int fc  = id & 7;
            float4 v = *(const float4*)(xb + (size_t)row * N_IN + fc * 4);
            float* dst = &xs[row * XS_PITCH + fc * 4];
            dst[0] = v.x; dst[1] = v.y; dst[2] = v.z; dst[3] = v.w;
        }
        // ---- stage 32x32 kernel block (1024 floats = 256 float4) ----
        {
            const float4* ksrc = (const float4*)(kern + (size_t)n * (BS * BS));
            ((float4*)ks)[tid]       = ksrc[tid];
            ((float4*)ks)[tid + 128] = ksrc[tid + 128];
        }
        __syncthreads();

        // ---- compute: acc[i][:] += x[row_i][k] * K[k][c0..c0+7] ----
#pragma unroll 4
        for (int k = 0; k < BS; k++) {
            float4 ka = *(const float4*)&ks[k * BS + c0];
            float4 kb = *(const float4*)&ks[k * BS + c0 + 4];
            unsigned long long kp[4];
            kp[0] = pack2(ka.x, ka.y);
            kp[1] = pack2(ka.z, ka.w);
            kp[2] = pack2(kb.x, kb.y);
            kp[3] = pack2(kb.z, kb.w);
#pragma unroll
            for (int i = 0; i < 8; i++) {
                float xv = xs[(rg + 32 * i) * XS_PITCH + k];
                unsigned long long xv2 = pack2(xv, xv);
#pragma unroll
                for (int j = 0; j < 4; j++) fma2(acc[i][j], xv2, kp[j]);
            }
        }
    }

    // ---- epilogue: bias + relu, write 256x32 tile ----
#pragma unroll
    for (int i = 0; i < 8; i++) {
        int row = bt * B_TILE + rg + 32 * i;
        float o[8];
#pragma unroll
        for (int j = 0; j < 4; j++) unpack2(acc[i][j], o[2 * j], o[2 * j + 1]);
#pragma unroll
        for (int j = 0; j < 8; j++) o[j] = fmaxf(o[j] + bb[j], 0.0f);
        float4 w0 = make_float4(o[0], o[1], o[2], o[3]);
        float4 w1 = make_float4(o[4], o[5], o[6], o[7]);
        float* dst = out + (size_t)row * N_OUT + cob * BS + c0;
        *(float4*)(dst)     = w0;
        *(float4*)(dst + 4) = w1;
    }
}

extern "C" void kernel_launch(void* const* d_in, const int* in_sizes, int n_in,
                              void* d_out, int out_size) {
    const float* x    = (const float*)d_in[0];
    const float* kern = (const float*)d_in[1];
    const float* bias = (const float*)d_in[2];
    const int*   ci   = (const int*)d_in[3];
    const int*   co   = (const int*)d_in[4];
    float* out = (float*)d_out;

    fill_tbl_kernel<<<(NB_I * NB_O + 255) / 256, 256>>>();
    scatter_tbl_kernel<<<(N_BLKS + 255) / 256, 256>>>(ci, co);

    dim3 grid(NB_O, BATCH / B_TILE);
    bs_main_kernel<<<grid, 128>>>(x, kern, bias, out);
}

// round 5
// speedup vs baseline: 1.6409x; 1.6409x over previous
#include <cuda_runtime.h>
#include <cstdint>

#define NB      128
#define CG      4              // block-columns per CTA
#define GROUPS  (NB / CG)      // 32
#define GCOLS   (CG * 32)      // 128
#define NTHR    256
#define MAXL    320
#define N_DIM   4096
#define BATCH   1024
#define NBLKS   4096

// SMEM layout (bytes, from dynamic base)
#define XS_STRIDE  36          // floats per row (4r+c bank-bijective)
#define BS_STRIDE  40          // floats per row (8k+n bank-bijective)
#define XS_SLOT    (128 * XS_STRIDE * 4)   // 18432
#define BS_SLOT    (32 * BS_STRIDE * 4)    // 5120
#define XS_OFF     0u
#define BS_OFF     (2u * XS_SLOT)                    // 36864
#define LIST_OFF   (BS_OFF + 2u * BS_SLOT)           // 47104
#define BIAS_OFF   (LIST_OFF + 4u * MAXL)            // 48384
#define SMEM_DYN   (BIAS_OFF + 4u * GCOLS)           // 48896

// ---------------- helpers ----------------

__device__ __forceinline__ uint32_t smem_u32(const void* p) {
    uint32_t a;
    asm("{ .reg .u64 t; cvta.to.shared.u64 t, %1; cvt.u32.u64 %0, t; }" : "=r"(a) : "l"(p));
    return a;
}
__device__ __forceinline__ void cpa16(uint32_t dst, const void* src) {
    asm volatile("cp.async.ca.shared.global [%0], [%1], 16;" :: "r"(dst), "l"(src));
}
#define CP_COMMIT() asm volatile("cp.async.commit_group;" ::: "memory")
#define CP_WAIT0()  asm volatile("cp.async.wait_group 0;" ::: "memory")

__device__ __forceinline__ float lds32(uint32_t a) {
    float v;
    asm volatile("ld.shared.f32 %0, [%1];" : "=f"(v) : "r"(a));
    return v;
}
// cvt.rna.tf32.f32 requires a .b32 destination register -> "=r"
__device__ __forceinline__ uint32_t tf32b(float a) {
    uint32_t r;
    asm("cvt.rna.tf32.f32 %0, %1;" : "=r"(r) : "f"(a));
    return r;
}

#define MMA_TF32(C, A0, A1, A2, A3, B0, B1)                                       \
    asm volatile("mma.sync.aligned.m16n8k8.row.col.f32.tf32.tf32.f32 "            \
                 "{%0,%1,%2,%3},{%4,%5,%6,%7},{%8,%9},{%0,%1,%2,%3};"             \
                 : "+f"((C)[0]), "+f"((C)[1]), "+f"((C)[2]), "+f"((C)[3])         \
                 : "r"(A0), "r"(A1), "r"(A2), "r"(A3), "r"(B0), "r"(B1))

// ---------------- work lists ----------------
// entry: n[0:12) | cib[12:19) | lco[19:21); list preserves sorted (ci,co) order.

__device__ int g_cnt[GROUPS];
__device__ int g_list[GROUPS * MAXL];

__global__ void build_lists_kernel(const int* __restrict__ ci, const int* __restrict__ co) {
    __shared__ int pref[NTHR];
    const int g = blockIdx.x;
    const int t = threadIdx.x;
    const int base = t * (NBLKS / NTHR);   // 16 entries per thread
    int cnt = 0;
#pragma unroll
    for (int j = 0; j < NBLKS / NTHR; j++)
        if ((co[base + j] >> 2) == g) cnt++;
    pref[t] = cnt;
    __syncthreads();
    for (int off = 1; off < NTHR; off <<= 1) {
        int v = (t >= off) ? pref[t - off] : 0;
        __syncthreads();
        pref[t] += v;
        __syncthreads();
    }
    int pos = pref[t] - cnt;
#pragma unroll
    for (int j = 0; j < NBLKS / NTHR; j++) {
        int n = base + j;
        int c = co[n];
        if ((c >> 2) == g) {
            g_list[g * MAXL + pos] = n | (ci[n] << 12) | ((c & 3) << 19);
            pos++;
        }
    }
    if (t == NTHR - 1) g_cnt[g] = pref[NTHR - 1];
}

// ---------------- per-block compute (LCO templated for const reg indexing) ----
// PTX m16n8k8.row.col A-fragment layout (row = lane>>2, col = lane&3):
//   a0=(row, col)  a1=(row+8, col)  a2=(row, col+4)  a3=(row+8, col+4)

template <int LCO>
__device__ __forceinline__ void compute_block(float (&acc)[16][4],
                                              uint32_t xs_warp, uint32_t bsb, int lane) {
    const int kq = lane & 3;
    const int nq = lane >> 2;

    // kernel fragments: b0=(k=kq, n=nq), b1=(k=kq+4, n=nq), rounded once to tf32
    uint32_t bfr[4][4][2];
#pragma unroll
    for (int kt = 0; kt < 4; kt++) {
#pragma unroll
        for (int nt = 0; nt < 4; nt++) {
            uint32_t a0 = bsb + 4u * ((uint32_t)(kt * 8 + kq) * BS_STRIDE + nt * 8 + nq);
            bfr[kt][nt][0] = tf32b(lds32(a0));
            bfr[kt][nt][1] = tf32b(lds32(a0 + 4u * 4 * BS_STRIDE));
        }
    }

#pragma unroll
    for (int kt = 0; kt < 4; kt++) {
        uint32_t r0 = xs_warp + 4u * ((uint32_t)nq * XS_STRIDE + kt * 8 + kq);
        float v_r0c0 = lds32(r0);                              // (row,   col)
        float v_r0c4 = lds32(r0 + 16u);                        // (row,   col+4)
        float v_r8c0 = lds32(r0 + 8u * XS_STRIDE * 4u);        // (row+8, col)
        float v_r8c4 = lds32(r0 + 8u * XS_STRIDE * 4u + 16u);  // (row+8, col+4)
        uint32_t ah0 = tf32b(v_r0c0), ah1 = tf32b(v_r8c0);
        uint32_t ah2 = tf32b(v_r0c4), ah3 = tf32b(v_r8c4);
        uint32_t al0 = tf32b(v_r0c0 - __uint_as_float(ah0));
        uint32_t al1 = tf32b(v_r8c0 - __uint_as_float(ah1));
        uint32_t al2 = tf32b(v_r0c4 - __uint_as_float(ah2));
        uint32_t al3 = tf32b(v_r8c4 - __uint_as_float(ah3));
#pragma unroll
        for (int nt = 0; nt < 4; nt++) {
            MMA_TF32(acc[4 * LCO + nt], ah0, ah1, ah2, ah3, bfr[kt][nt][0], bfr[kt][nt][1]);
            MMA_TF32(acc[4 * LCO + nt], al0, al1, al2, al3, bfr[kt][nt][0], bfr[kt][nt][1]);
        }
    }
}

// ---------------- main kernel ----------------

__global__ void __launch_bounds__(NTHR, 1)
bs_mma_kernel(const float* __restrict__ x, const float* __restrict__ kern,
              const float* __restrict__ bias, float* __restrict__ out) {
    extern __shared__ char smem_raw[];
    const uint32_t base = smem_u32(smem_raw);
    int* list_s = (int*)(smem_raw + LIST_OFF);
    float* bias_s = (float*)(smem_raw + BIAS_OFF);

    const int g   = blockIdx.x;
    const int by  = blockIdx.y;
    const int tid = threadIdx.x;
    const int w   = tid >> 5;
    const int lane = tid & 31;

    const int cnt = g_cnt[g];
    for (int j = tid; j < cnt; j += NTHR) list_s[j] = g_list[g * MAXL + j];
    if (tid < GCOLS) bias_s[tid] = bias[g * GCOLS + tid];
    __syncthreads();

    float acc[16][4];
#pragma unroll
    for (int i = 0; i < 16; i++)
#pragma unroll
        for (int j = 0; j < 4; j++) acc[i][j] = 0.f;

    const float* xrow0 = x + (size_t)(by * 128) * N_DIM;

    auto stage_x = [&](int cib, int slot) {
        const float* src = xrow0 + cib * 32;
        uint32_t dst = base + XS_OFF + (uint32_t)slot * XS_SLOT;
#pragma unroll
        for (int j = 0; j < 4; j++) {
            int id = tid + j * NTHR;        // 0..1023
            int row = id >> 3, c4 = id & 7;
            cpa16(dst + (uint32_t)row * (XS_STRIDE * 4) + c4 * 16u,
                  src + (size_t)row * N_DIM + c4 * 4);
        }
    };
    auto stage_b = [&](int n, int slot) {
        const float* src = kern + (size_t)n * 1024;
        uint32_t dst = base + BS_OFF + (uint32_t)slot * BS_SLOT;
        int row = tid >> 3, c4 = tid & 7;   // 256 chunks of 16B
        cpa16(dst + (uint32_t)row * (BS_STRIDE * 4) + c4 * 16u, src + row * 32 + c4 * 4);
    };

    if (cnt > 0) {
        int v0 = list_s[0];
        int cib_cur = (v0 >> 12) & 127;
        stage_x(cib_cur, 0);
        stage_b(v0 & 0xFFF, 0);
        CP_COMMIT();
        int xslot = 0;

        for (int i = 0; i < cnt; i++) {
            int vi = list_s[i];
            int lco = (vi >> 19) & 3;
            CP_WAIT0();
            __syncthreads();

            int x_next = xslot;
            if (i + 1 < cnt) {
                int v1 = list_s[i + 1];
                int cib1 = (v1 >> 12) & 127;
                if (cib1 != cib_cur) {
                    x_next = xslot ^ 1;
                    stage_x(cib1, x_next);
                    cib_cur = cib1;
                }
                stage_b(v1 & 0xFFF, (i + 1) & 1);
                CP_COMMIT();
            }

            uint32_t xs_warp = base + XS_OFF + (uint32_t)xslot * XS_SLOT + (uint32_t)(16 * w) * (XS_STRIDE * 4);
            uint32_t bsb     = base + BS_OFF + (uint32_t)(i & 1) * BS_SLOT;
            switch (lco) {
                case 0: compute_block<0>(acc, xs_warp, bsb, lane); break;
                case 1: compute_block<1>(acc, xs_warp, bsb, lane); break;
                case 2: compute_block<2>(acc, xs_warp, bsb, lane); break;
                default: compute_block<3>(acc, xs_warp, bsb, lane); break;
            }
            xslot = x_next;
        }
    }

    // ---- epilogue: bias + relu ----
    {
        int r = 16 * w + (lane >> 2);
        size_t rb0 = (size_t)(by * 128 + r) * N_DIM + g * GCOLS;
        size_t rb1 = rb0 + 8 * (size_t)N_DIM;
#pragma unroll
        for (int nt = 0; nt < 16; nt++) {
            int c = nt * 8 + 2 * (lane & 3);
            float b0 = bias_s[c], b1 = bias_s[c + 1];
            float2 v0, v1;
            v0.x = fmaxf(acc[nt][0] + b0, 0.f);
            v0.y = fmaxf(acc[nt][1] + b1, 0.f);
            v1.x = fmaxf(acc[nt][2] + b0, 0.f);
            v1.y = fmaxf(acc[nt][3] + b1, 0.f);
            *(float2*)(out + rb0 + c) = v0;
            *(float2*)(out + rb1 + c) = v1;
        }
    }
}

extern "C" void kernel_launch(void* const* d_in, const int* in_sizes, int n_in,
                              void* d_out, int out_size) {
    const float* x    = (const float*)d_in[0];
    const float* kern = (const float*)d_in[1];
    const float* bias = (const float*)d_in[2];
    const int*   ci   = (const int*)d_in[3];
    const int*   co   = (const int*)d_in[4];
    float* out = (float*)d_out;

    cudaFuncSetAttribute(bs_mma_kernel, cudaFuncAttributeMaxDynamicSharedMemorySize, SMEM_DYN);

    build_lists_kernel<<<GROUPS, NTHR>>>(ci, co);
    dim3 grid(GROUPS, BATCH / 128);
    bs_mma_kernel<<<grid, NTHR, SMEM_DYN>>>(x, kern, bias, out);
}

// round 6
// speedup vs baseline: 1.6714x; 1.0186x over previous
#include <cuda_runtime.h>
#include <cstdint>

#define NB      128
#define CG      4              // block-columns per CTA
#define GROUPS  (NB / CG)      // 32
#define GCOLS   (CG * 32)      // 128
#define NTHR    256
#define MAXL    320
#define N_DIM   4096
#define BATCH   1024
#define NBLKS   4096

// SMEM layout (bytes, from dynamic base)
#define XS_STRIDE  36          // floats per row (bank-bijective for frag loads)
#define XS_SLOT    (128 * XS_STRIDE * 4)   // 18432
// B stored pre-converted to tf32 in paired layout:
//   pair-row pr = (k>>3)*4 + (k&3)  (16 rows), element e = (k>>2)&1
//   float2 slot [pr][n] holds {B[k][n], B[k+4][n]}, pitch 40 float2 = 320B
#define BP_PITCH   40          // float2 units per pair-row (conflict-free frag loads)
#define BS_SLOT    (16 * BP_PITCH * 8)     // 5120
#define XS_OFF     0u
#define BS_OFF     (2u * XS_SLOT)                    // 36864
#define LIST_OFF   (BS_OFF + 2u * BS_SLOT)           // 47104
#define BIAS_OFF   (LIST_OFF + 4u * MAXL)            // 48384
#define SMEM_DYN   (BIAS_OFF + 4u * GCOLS)           // 48896

// ---------------- helpers ----------------

__device__ __forceinline__ uint32_t smem_u32(const void* p) {
    uint32_t a;
    asm("{ .reg .u64 t; cvta.to.shared.u64 t, %1; cvt.u32.u64 %0, t; }" : "=r"(a) : "l"(p));
    return a;
}
__device__ __forceinline__ void cpa16(uint32_t dst, const void* src) {
    asm volatile("cp.async.ca.shared.global [%0], [%1], 16;" :: "r"(dst), "l"(src));
}
#define CP_COMMIT() asm volatile("cp.async.commit_group;" ::: "memory")
#define CP_WAIT0()  asm volatile("cp.async.wait_group 0;" ::: "memory")

__device__ __forceinline__ float lds32(uint32_t a) {
    float v;
    asm volatile("ld.shared.f32 %0, [%1];" : "=f"(v) : "r"(a));
    return v;
}
__device__ __forceinline__ void lds64(uint32_t a, uint32_t& r0, uint32_t& r1) {
    asm volatile("ld.shared.v2.b32 {%0,%1}, [%2];" : "=r"(r0), "=r"(r1) : "r"(a));
}
__device__ __forceinline__ void sts32(uint32_t a, uint32_t v) {
    asm volatile("st.shared.b32 [%0], %1;" :: "r"(a), "r"(v));
}
// cvt.rna.tf32.f32 requires a .b32 destination register -> "=r"
__device__ __forceinline__ uint32_t tf32b(float a) {
    uint32_t r;
    asm("cvt.rna.tf32.f32 %0, %1;" : "=r"(r) : "f"(a));
    return r;
}

#define MMA_TF32(C, A0, A1, A2, A3, B0, B1)                                       \
    asm volatile("mma.sync.aligned.m16n8k8.row.col.f32.tf32.tf32.f32 "            \
                 "{%0,%1,%2,%3},{%4,%5,%6,%7},{%8,%9},{%0,%1,%2,%3};"             \
                 : "+f"((C)[0]), "+f"((C)[1]), "+f"((C)[2]), "+f"((C)[3])         \
                 : "r"(A0), "r"(A1), "r"(A2), "r"(A3), "r"(B0), "r"(B1))

// ---------------- work lists ----------------
// entry: n[0:12) | cib[12:19) | lco[19:21); list preserves sorted (ci,co) order.

__device__ int g_cnt[GROUPS];
__device__ int g_list[GROUPS * MAXL];

__global__ void build_lists_kernel(const int* __restrict__ ci, const int* __restrict__ co) {
    __shared__ int pref[NTHR];
    const int g = blockIdx.x;
    const int t = threadIdx.x;
    const int base = t * (NBLKS / NTHR);   // 16 entries per thread
    int cnt = 0;
#pragma unroll
    for (int j = 0; j < NBLKS / NTHR; j++)
        if ((co[base + j] >> 2) == g) cnt++;
    pref[t] = cnt;
    __syncthreads();
    for (int off = 1; off < NTHR; off <<= 1) {
        int v = (t >= off) ? pref[t - off] : 0;
        __syncthreads();
        pref[t] += v;
        __syncthreads();
    }
    int pos = pref[t] - cnt;
#pragma unroll
    for (int j = 0; j < NBLKS / NTHR; j++) {
        int n = base + j;
        int c = co[n];
        if ((c >> 2) == g) {
            g_list[g * MAXL + pos] = n | (ci[n] << 12) | ((c & 3) << 19);
            pos++;
        }
    }
    if (t == NTHR - 1) g_cnt[g] = pref[NTHR - 1];
}

// ---------------- per-block compute ----------------
// PTX m16n8k8.row.col A layout (row = lane>>2, col = lane&3):
//   a0=(row,col) a1=(row+8,col) a2=(row,col+4) a3=(row+8,col+4)
// B layout: b0=(k=lane&3, n=lane>>2), b1=(k+4, n)  -> one LDS.64 in pair layout.

template <int LCO>
__device__ __forceinline__ void compute_block(float (&acc)[16][4],
                                              const uint32_t (&afr)[4][4],
                                              uint32_t bsb, int kq, int nq) {
#pragma unroll
    for (int kt = 0; kt < 4; kt++) {
#pragma unroll
        for (int nt = 0; nt < 4; nt++) {
            uint32_t b0, b1;
            lds64(bsb + 8u * ((uint32_t)(kt * 4 + kq) * BP_PITCH + nt * 8 + nq), b0, b1);
            MMA_TF32(acc[4 * LCO + nt], afr[kt][0], afr[kt][1], afr[kt][2], afr[kt][3], b0, b1);
        }
    }
}

__device__ __forceinline__ void load_afrags(uint32_t (&afr)[4][4], uint32_t xs_warp,
                                            int kq, int nq) {
#pragma unroll
    for (int kt = 0; kt < 4; kt++) {
        uint32_t r0 = xs_warp + 4u * ((uint32_t)nq * XS_STRIDE + kt * 8 + kq);
        afr[kt][0] = tf32b(lds32(r0));                              // (row,   col)
        afr[kt][1] = tf32b(lds32(r0 + 8u * XS_STRIDE * 4u));        // (row+8, col)
        afr[kt][2] = tf32b(lds32(r0 + 16u));                        // (row,   col+4)
        afr[kt][3] = tf32b(lds32(r0 + 8u * XS_STRIDE * 4u + 16u));  // (row+8, col+4)
    }
}

// ---------------- main kernel ----------------

__global__ void __launch_bounds__(NTHR, 2)
bs_mma_kernel(const float* __restrict__ x, const float* __restrict__ kern,
              const float* __restrict__ bias, float* __restrict__ out) {
    extern __shared__ char smem_raw[];
    const uint32_t base = smem_u32(smem_raw);
    int* list_s = (int*)(smem_raw + LIST_OFF);
    float* bias_s = (float*)(smem_raw + BIAS_OFF);

    const int g   = blockIdx.x;
    const int by  = blockIdx.y;
    const int tid = threadIdx.x;
    const int w   = tid >> 5;
    const int lane = tid & 31;
    const int kq  = lane & 3;
    const int nq  = lane >> 2;

    const int cnt = g_cnt[g];
    for (int j = tid; j < cnt; j += NTHR) list_s[j] = g_list[g * MAXL + j];
    if (tid < GCOLS) bias_s[tid] = bias[g * GCOLS + tid];

    float acc[16][4];
#pragma unroll
    for (int i = 0; i < 16; i++)
#pragma unroll
        for (int j = 0; j < 4; j++) acc[i][j] = 0.f;

    const float* xrow0 = x + (size_t)(by * 128) * N_DIM;

    auto stage_x = [&](int cib, int slot) {
        const float* src = xrow0 + cib * 32;
        uint32_t dst = base + XS_OFF + (uint32_t)slot * XS_SLOT;
#pragma unroll
        for (int j = 0; j < 4; j++) {
            int id = tid + j * NTHR;        // 0..1023 float4 slots
            int row = id >> 3, c4 = id & 7;
            cpa16(dst + (uint32_t)row * (XS_STRIDE * 4) + c4 * 16u,
                  src + (size_t)row * N_DIM + c4 * 4);
        }
    };
    // B: this thread owns row k = tid>>3, cols n0..n0+3 (n0 = 4*(tid&7))
    auto ldg_b = [&](int n) -> float4 {
        return *(const float4*)(kern + (size_t)n * 1024 + tid * 4);
    };
    auto sts_b = [&](float4 v, int slot) {
        int k  = tid >> 3;
        int n0 = 4 * (tid & 7);
        int pr = ((k >> 3) << 2) | (k & 3);
        int e  = (k >> 2) & 1;
        uint32_t a0 = base + BS_OFF + (uint32_t)slot * BS_SLOT +
                      (uint32_t)pr * (BP_PITCH * 8) + (uint32_t)e * 4 + (uint32_t)n0 * 8;
        sts32(a0,       tf32b(v.x));
        sts32(a0 + 8u,  tf32b(v.y));
        sts32(a0 + 16u, tf32b(v.z));
        sts32(a0 + 24u, tf32b(v.w));
    };

    if (cnt > 0) {
        uint32_t afr[4][4];
        int v0 = list_s[0];        // list_s written by this thread's own loop? no:
        // list_s may not be visible yet -> must sync before reading. Use g_list direct.
        v0 = g_list[g * MAXL + 0];
        int cib_cur = (v0 >> 12) & 127;
        stage_x(cib_cur, 0);
        CP_COMMIT();
        float4 breg = ldg_b(v0 & 0xFFF);
        sts_b(breg, 0);
        CP_WAIT0();
        __syncthreads();

        int xslot = 0;
        int frag_cib = -1;

        for (int i = 0; i < cnt; i++) {
            int vi  = list_s[i];
            int lco = (vi >> 19) & 3;
            int cib_i = (vi >> 12) & 127;

            if (cib_i != frag_cib) {
                load_afrags(afr, base + XS_OFF + (uint32_t)xslot * XS_SLOT +
                                 (uint32_t)(16 * w) * (XS_STRIDE * 4), kq, nq);
                frag_cib = cib_i;
            }

            int x_next = xslot;
            bool have_next = (i + 1 < cnt);
            int cib1 = cib_i;
            if (have_next) {
                int v1 = list_s[i + 1];
                cib1 = (v1 >> 12) & 127;
                breg = ldg_b(v1 & 0xFFF);
                if (cib1 != cib_i) {
                    x_next = xslot ^ 1;
                    stage_x(cib1, x_next);
                    CP_COMMIT();
                }
            }

            uint32_t bsb = base + BS_OFF + (uint32_t)(i & 1) * BS_SLOT;
            switch (lco) {
                case 0: compute_block<0>(acc, afr, bsb, kq, nq); break;
                case 1: compute_block<1>(acc, afr, bsb, kq, nq); break;
                case 2: compute_block<2>(acc, afr, bsb, kq, nq); break;
                default: compute_block<3>(acc, afr, bsb, kq, nq); break;
            }

            if (have_next) sts_b(breg, (i + 1) & 1);
            CP_WAIT0();
            __syncthreads();
            xslot = x_next;
        }
    } else {
        __syncthreads();   // make bias_s visible for epilogue
    }

    // ---- epilogue: bias + relu ----
    {
        int r = 16 * w + nq;
        size_t rb0 = (size_t)(by * 128 + r) * N_DIM + g * GCOLS;
        size_t rb1 = rb0 + 8 * (size_t)N_DIM;
#pragma unroll
        for (int nt = 0; nt < 16; nt++) {
            int c = nt * 8 + 2 * kq;
            float b0 = bias_s[c], b1 = bias_s[c + 1];
            float2 v0, v1;
            v0.x = fmaxf(acc[nt][0] + b0, 0.f);
            v0.y = fmaxf(acc[nt][1] + b1, 0.f);
            v1.x = fmaxf(acc[nt][2] + b0, 0.f);
            v1.y = fmaxf(acc[nt][3] + b1, 0.f);
            *(float2*)(out + rb0 + c) = v0;
            *(float2*)(out + rb1 + c) = v1;
        }
    }
}

extern "C" void kernel_launch(void* const* d_in, const int* in_sizes, int n_in,
                              void* d_out, int out_size) {
    const float* x    = (const float*)d_in[0];
    const float* kern = (const float*)d_in[1];
    const float* bias = (const float*)d_in[2];
    const int*   ci   = (const int*)d_in[3];
    const int*   co   = (const int*)d_in[4];
    float* out = (float*)d_out;

    cudaFuncSetAttribute(bs_mma_kernel, cudaFuncAttributeMaxDynamicSharedMemorySize, SMEM_DYN);

    build_lists_kernel<<<GROUPS, NTHR>>>(ci, co);
    dim3 grid(GROUPS, BATCH / 128);
    bs_mma_kernel<<<grid, NTHR, SMEM_DYN>>>(x, kern, bias, out);
}

// round 7
// speedup vs baseline: 2.1609x; 1.2929x over previous
#include <cuda_runtime.h>
#include <cstdint>

#define NB      128
#define CG      4              // block-columns per CTA
#define GROUPS  (NB / CG)      // 32
#define GCOLS   (CG * 32)      // 128
#define NTHR    256
#define MAXL    320
#define N_DIM   4096
#define BATCH   1024
#define NBLKS   4096

// SMEM layout (bytes, from dynamic base)
#define XS_STRIDE  36          // floats per row (bank-bijective frag loads)
#define XS_SLOT    (128 * XS_STRIDE * 4)   // 18432
#define BR_PITCH   40          // floats per raw-B row: kq*40+nq spans banks 0..31
#define BR_SLOT    (32 * BR_PITCH * 4)     // 5120
#define XS_OFF     0u
#define BR_OFF     (4u * XS_SLOT)                    // 73728
#define LIST_OFF   (BR_OFF + 4u * BR_SLOT)           // 94208
#define BIAS_OFF   (LIST_OFF + 4u * MAXL)            // 95488
#define SMEM_DYN   (BIAS_OFF + 4u * GCOLS)           // 96000

// ---------------- helpers ----------------

__device__ __forceinline__ uint32_t smem_u32(const void* p) {
    uint32_t a;
    asm("{ .reg .u64 t; cvta.to.shared.u64 t, %1; cvt.u32.u64 %0, t; }" : "=r"(a) : "l"(p));
    return a;
}
__device__ __forceinline__ void cpa16(uint32_t dst, const void* src) {
    asm volatile("cp.async.ca.shared.global [%0], [%1], 16;" :: "r"(dst), "l"(src));
}
#define CP_COMMIT() asm volatile("cp.async.commit_group;" ::: "memory")
#define CP_WAIT2()  asm volatile("cp.async.wait_group 2;" ::: "memory")

__device__ __forceinline__ float lds32(uint32_t a) {
    float v;
    asm volatile("ld.shared.f32 %0, [%1];" : "=f"(v) : "r"(a));
    return v;
}
// cvt.rna.tf32.f32 requires a .b32 destination register -> "=r"
__device__ __forceinline__ uint32_t tf32b(float a) {
    uint32_t r;
    asm("cvt.rna.tf32.f32 %0, %1;" : "=r"(r) : "f"(a));
    return r;
}

#define MMA_TF32(C, A0, A1, A2, A3, B0, B1)                                       \
    asm volatile("mma.sync.aligned.m16n8k8.row.col.f32.tf32.tf32.f32 "            \
                 "{%0,%1,%2,%3},{%4,%5,%6,%7},{%8,%9},{%0,%1,%2,%3};"             \
                 : "+f"((C)[0]), "+f"((C)[1]), "+f"((C)[2]), "+f"((C)[3])         \
                 : "r"(A0), "r"(A1), "r"(A2), "r"(A3), "r"(B0), "r"(B1))

// ---------------- work lists ----------------
// entry: n[0:12) | cib[12:19) | lco[19:21); list preserves sorted (ci,co) order.

__device__ int g_cnt[GROUPS];
__device__ int g_list[GROUPS * MAXL];

__global__ void build_lists_kernel(const int* __restrict__ ci, const int* __restrict__ co) {
    __shared__ int pref[NTHR];
    const int g = blockIdx.x;
    const int t = threadIdx.x;
    const int base = t * (NBLKS / NTHR);   // 16 entries per thread
    int cnt = 0;
#pragma unroll
    for (int j = 0; j < NBLKS / NTHR; j++)
        if ((co[base + j] >> 2) == g) cnt++;
    pref[t] = cnt;
    __syncthreads();
    for (int off = 1; off < NTHR; off <<= 1) {
        int v = (t >= off) ? pref[t - off] : 0;
        __syncthreads();
        pref[t] += v;
        __syncthreads();
    }
    int pos = pref[t] - cnt;
#pragma unroll
    for (int j = 0; j < NBLKS / NTHR; j++) {
        int n = base + j;
        int c = co[n];
        if ((c >> 2) == g) {
            g_list[g * MAXL + pos] = n | (ci[n] << 12) | ((c & 3) << 19);
            pos++;
        }
    }
    if (t == NTHR - 1) g_cnt[g] = pref[NTHR - 1];
}

// ---------------- per-block compute ----------------
// PTX m16n8k8.row.col A layout (row = lane>>2, col = lane&3):
//   a0=(row,col) a1=(row+8,col) a2=(row,col+4) a3=(row+8,col+4)
// B fragment: b0=(k=lane&3, n=lane>>2), b1=(k+4, n); read from raw-B row-major
// (pitch 40 floats) with inline tf32 cvt.

template <int LCO>
__device__ __forceinline__ void compute_block(float (&acc)[16][4],
                                              const uint32_t (&afr)[4][4],
                                              uint32_t brb, int kq, int nq) {
#pragma unroll
    for (int kt = 0; kt < 4; kt++) {
        uint32_t rowa = brb + 4u * ((uint32_t)(kt * 8 + kq) * BR_PITCH + nq);
#pragma unroll
        for (int nt = 0; nt < 4; nt++) {
            uint32_t a  = rowa + 4u * (uint32_t)(nt * 8);
            uint32_t b0 = tf32b(lds32(a));
            uint32_t b1 = tf32b(lds32(a + 4u * 4 * BR_PITCH));
            MMA_TF32(acc[4 * LCO + nt], afr[kt][0], afr[kt][1], afr[kt][2], afr[kt][3], b0, b1);
        }
    }
}

__device__ __forceinline__ void load_afrags(uint32_t (&afr)[4][4], uint32_t xs_warp,
                                            int kq, int nq) {
#pragma unroll
    for (int kt = 0; kt < 4; kt++) {
        uint32_t r0 = xs_warp + 4u * ((uint32_t)nq * XS_STRIDE + kt * 8 + kq);
        afr[kt][0] = tf32b(lds32(r0));                              // (row,   col)
        afr[kt][1] = tf32b(lds32(r0 + 8u * XS_STRIDE * 4u));        // (row+8, col)
        afr[kt][2] = tf32b(lds32(r0 + 16u));                        // (row,   col+4)
        afr[kt][3] = tf32b(lds32(r0 + 8u * XS_STRIDE * 4u + 16u));  // (row+8, col+4)
    }
}

// ---------------- main kernel ----------------

__global__ void __launch_bounds__(NTHR, 2)
bs_mma_kernel(const float* __restrict__ x, const float* __restrict__ kern,
              const float* __restrict__ bias, float* __restrict__ out) {
    extern __shared__ char smem_raw[];
    const uint32_t base = smem_u32(smem_raw);
    int* list_s = (int*)(smem_raw + LIST_OFF);
    float* bias_s = (float*)(smem_raw + BIAS_OFF);

    const int g   = blockIdx.x;
    const int by  = blockIdx.y;
    const int tid = threadIdx.x;
    const int w   = tid >> 5;
    const int lane = tid & 31;
    const int kq  = lane & 3;
    const int nq  = lane >> 2;

    const int cnt = g_cnt[g];
    for (int j = tid; j < cnt; j += NTHR) list_s[j] = g_list[g * MAXL + j];
    if (tid < GCOLS) bias_s[tid] = bias[g * GCOLS + tid];
    __syncthreads();

    float acc[16][4];
#pragma unroll
    for (int i = 0; i < 16; i++)
#pragma unroll
        for (int j = 0; j < 4; j++) acc[i][j] = 0.f;

    const float* xrow0 = x + (size_t)(by * 128) * N_DIM;

    auto stage_x = [&](int cib, int slot) {
        const float* src = xrow0 + cib * 32;
        uint32_t dst = base + XS_OFF + (uint32_t)slot * XS_SLOT;
#pragma unroll
        for (int j = 0; j < 4; j++) {
            int id = tid + j * NTHR;        // 0..1023 float4 slots
            int row = id >> 3, c4 = id & 7;
            cpa16(dst + (uint32_t)row * (XS_STRIDE * 4) + c4 * 16u,
                  src + (size_t)row * N_DIM + c4 * 4);
        }
    };
    auto stage_braw = [&](int n, int slot) {
        int k  = tid >> 3;
        int n0 = 4 * (tid & 7);
        cpa16(base + BR_OFF + (uint32_t)slot * BR_SLOT + 4u * ((uint32_t)k * BR_PITCH + n0),
              kern + (size_t)n * 1024 + k * 32 + n0);
    };

    if (cnt > 0) {
        // prefetch state: slot shift-queue s0 (iter i), s1 (i+1), s2 (i+2)
        int staged_cib = -1, staged_slot = 3;
        int s0 = 0, s1 = 0, s2 = 0;

        auto prefetch = [&](int j) -> int {
            int e = list_s[j];
            int cib = (e >> 12) & 127;
            if (cib != staged_cib) {
                staged_slot = (staged_slot + 1) & 3;
                stage_x(cib, staged_slot);
                staged_cib = cib;
            }
            stage_braw(e & 0xFFF, j & 3);
            return staged_slot;
        };

        s0 = prefetch(0);
        CP_COMMIT();
        if (cnt > 1) s1 = prefetch(1);
        CP_COMMIT();

        uint32_t afr[4][4];
        int frag_cib = -1;

        for (int i = 0; i < cnt; i++) {
            if (i + 2 < cnt) s2 = prefetch(i + 2);
            CP_COMMIT();
            CP_WAIT2();            // group for iter i (committed 2 iters ago) complete
            __syncthreads();       // all threads' staging for iter i visible

            int vi  = list_s[i];
            int lco = (vi >> 19) & 3;
            int cib_i = (vi >> 12) & 127;

            if (cib_i != frag_cib) {
                load_afrags(afr, base + XS_OFF + (uint32_t)s0 * XS_SLOT +
                                 (uint32_t)(16 * w) * (XS_STRIDE * 4), kq, nq);
                frag_cib = cib_i;
            }

            uint32_t brb = base + BR_OFF + (uint32_t)(i & 3) * BR_SLOT;
            switch (lco) {
                case 0: compute_block<0>(acc, afr, brb, kq, nq); break;
                case 1: compute_block<1>(acc, afr, brb, kq, nq); break;
                case 2: compute_block<2>(acc, afr, brb, kq, nq); break;
                default: compute_block<3>(acc, afr, brb, kq, nq); break;
            }

            s0 = s1; s1 = s2;
        }
    }

    // ---- epilogue: bias + relu ----
    {
        int r = 16 * w + nq;
        size_t rb0 = (size_t)(by * 128 + r) * N_DIM + g * GCOLS;
        size_t rb1 = rb0 + 8 * (size_t)N_DIM;
#pragma unroll
        for (int nt = 0; nt < 16; nt++) {
            int c = nt * 8 + 2 * kq;
            float b0 = bias_s[c], b1 = bias_s[c + 1];
            float2 v0, v1;
            v0.x = fmaxf(acc[nt][0] + b0, 0.f);
            v0.y = fmaxf(acc[nt][1] + b1, 0.f);
            v1.x = fmaxf(acc[nt][2] + b0, 0.f);
            v1.y = fmaxf(acc[nt][3] + b1, 0.f);
            *(float2*)(out + rb0 + c) = v0;
            *(float2*)(out + rb1 + c) = v1;
        }
    }
}

extern "C" void kernel_launch(void* const* d_in, const int* in_sizes, int n_in,
                              void* d_out, int out_size) {
    const float* x    = (const float*)d_in[0];
    const float* kern = (const float*)d_in[1];
    const float* bias = (const float*)d_in[2];
    const int*   ci   = (const int*)d_in[3];
    const int*   co   = (const int*)d_in[4];
    float* out = (float*)d_out;

    cudaFuncSetAttribute(bs_mma_kernel, cudaFuncAttributeMaxDynamicSharedMemorySize, SMEM_DYN);

    build_lists_kernel<<<GROUPS, NTHR>>>(ci, co);
    dim3 grid(GROUPS, BATCH / 128);
    bs_mma_kernel<<<grid, NTHR, SMEM_DYN>>>(x, kern, bias, out);
}